// round 7
// baseline (speedup 1.0000x reference)
#include <cuda_runtime.h>
#include <cstdint>

// Problem constants: B=1024, FANOUTS=[10,25], DIM=256, N_NODES=100000
#define DIM   256
#define D4    64      // DIM / 4

typedef unsigned long long u64;

// Scratch (device globals; allocation-free per harness rules)
__device__ float g_n1[10240 * DIM];   // layer0 output on hop-1 nodes
__device__ float g_n0[1024  * DIM];   // layer0 output on hop-0 nodes
__device__ float g_Wt0[256 * 256];    // layer0 packed weights
__device__ float g_Wt1[256 * 256];    // layer1 packed weights

__device__ __forceinline__ u64 ffma2(u64 a, u64 b, u64 c) {
    u64 d;
    asm("fma.rn.f32x2 %0, %1, %2, %3;" : "=l"(d) : "l"(a), "l"(b), "l"(c));
    return d;
}

// Pack [Ws|Wn] (each [256,128] row-major) into Wt[k/8][c][k%8],
// c in [0,256): 0-127 self cols, 128-255 neigh cols. Writes coalesced.
__global__ void __launch_bounds__(256)
pack_weights(const float* __restrict__ W0s, const float* __restrict__ W0n,
             const float* __restrict__ W1s, const float* __restrict__ W1n)
{
    const int idx = blockIdx.x * 256 + threadIdx.x;   // 0 .. 131071
    const int l   = idx >> 16;
    const int rem = idx & 65535;
    const int k8  = rem >> 11;
    const int c   = (rem >> 3) & 255;
    const int k0  = rem & 7;
    const int k   = k8 * 8 + k0;
    const float* Ws = l ? W1s : W0s;
    const float* Wn = l ? W1n : W0n;
    const float v = (c < 128) ? __ldg(Ws + k * 128 + c)
                              : __ldg(Wn + k * 128 + (c - 128));
    (l ? g_Wt1 : g_Wt0)[rem] = v;
}

// ---- warp-cooperative row ops: 32 lanes cover 64 float4 slots of one row ---
__device__ __forceinline__ void warp_load_row(
    const float4* __restrict__ src4, size_t row, int lane,
    float4& v0, float4& v1)
{
    v0 = __ldcg(src4 + row * D4 + lane);        // coalesced 512B
    v1 = __ldcg(src4 + row * D4 + 32 + lane);   // coalesced 512B
}

template <int F, bool IDX>
__device__ __forceinline__ void warp_mean_rows(
    const float4* __restrict__ src4, const int* __restrict__ nidx,
    size_t nb, int lane, float4& out0, float4& out1)
{
    float4 a00 = make_float4(0.f,0.f,0.f,0.f), a01 = a00, a10 = a00, a11 = a00;
    #pragma unroll
    for (int j = 0; j < F; j += 2) {
        const size_t g0 = IDX ? (size_t)__ldg(nidx + nb + j) : (nb + j);
        float4 v0, v1;
        warp_load_row(src4, g0, lane, v0, v1);
        a00.x += v0.x; a00.y += v0.y; a00.z += v0.z; a00.w += v0.w;
        a01.x += v1.x; a01.y += v1.y; a01.z += v1.z; a01.w += v1.w;
        if (j + 1 < F) {
            const size_t g1 = IDX ? (size_t)__ldg(nidx + nb + j + 1) : (nb + j + 1);
            float4 w0, w1;
            warp_load_row(src4, g1, lane, w0, w1);
            a10.x += w0.x; a10.y += w0.y; a10.z += w0.z; a10.w += w0.w;
            a11.x += w1.x; a11.y += w1.y; a11.z += w1.z; a11.w += w1.w;
        }
    }
    const float inv = 1.0f / (float)F;
    out0.x = (a00.x + a10.x) * inv; out0.y = (a00.y + a10.y) * inv;
    out0.z = (a00.z + a10.z) * inv; out0.w = (a00.w + a10.w) * inv;
    out1.x = (a01.x + a11.x) * inv; out1.y = (a01.y + a11.y) * inv;
    out1.z = (a01.z + a11.z) * inv; out1.w = (a01.w + a11.w) * inv;
}

// ---- GEMM phase: thread -> (column pair (c2, c2+128), RPT rows) ------------
template <int TM, int THREADS, bool RELU>
__device__ __forceinline__ void gemm_tile(
    const float4* Xs4, const float4* Xn4,
    const float* __restrict__ Wt,    // packed [32][256][8]
    float* __restrict__ out, int m0)
{
    constexpr int RG  = THREADS / 128;
    constexpr int RPT = TM / RG;
    const int tid = threadIdx.x;
    const int c2  = tid & 127;
    const int r0  = (tid >> 7) * RPT;
    const float* Xs = reinterpret_cast<const float*>(Xs4);
    const float* Xn = reinterpret_cast<const float*>(Xn4);
    const ulonglong2* __restrict__ Wt2 = reinterpret_cast<const ulonglong2*>(Wt);

    u64 accA[RPT], accB[RPT];
    #pragma unroll
    for (int r = 0; r < RPT; ++r) { accA[r] = 0ull; accB[r] = 0ull; }

    #pragma unroll 2
    for (int kb = 0; kb < 32; ++kb) {            // 8 k-values per iteration
        const int base = kb * 512;               // ulonglong2 units per block
        const ulonglong2 wa0 = __ldg(Wt2 + base + c2 * 2);
        const ulonglong2 wa1 = __ldg(Wt2 + base + c2 * 2 + 1);
        const ulonglong2 wb0 = __ldg(Wt2 + base + (128 + c2) * 2);
        const ulonglong2 wb1 = __ldg(Wt2 + base + (128 + c2) * 2 + 1);
        #pragma unroll
        for (int r = 0; r < RPT; ++r) {
            const float* xsr = Xs + (r0 + r) * DIM + kb * 8;   // warp-uniform
            const ulonglong2 xs0 = *reinterpret_cast<const ulonglong2*>(xsr);
            const ulonglong2 xs1 = *reinterpret_cast<const ulonglong2*>(xsr + 4);
            accA[r] = ffma2(xs0.x, wa0.x, accA[r]);
            accA[r] = ffma2(xs0.y, wa0.y, accA[r]);
            accA[r] = ffma2(xs1.x, wa1.x, accA[r]);
            accA[r] = ffma2(xs1.y, wa1.y, accA[r]);
            const float* xnr = Xn + (r0 + r) * DIM + kb * 8;
            const ulonglong2 xn0 = *reinterpret_cast<const ulonglong2*>(xnr);
            const ulonglong2 xn1 = *reinterpret_cast<const ulonglong2*>(xnr + 4);
            accB[r] = ffma2(xn0.x, wb0.x, accB[r]);
            accB[r] = ffma2(xn0.y, wb0.y, accB[r]);
            accB[r] = ffma2(xn1.x, wb1.x, accB[r]);
            accB[r] = ffma2(xn1.y, wb1.y, accB[r]);
        }
    }

    #pragma unroll
    for (int r = 0; r < RPT; ++r) {
        float vA = __uint_as_float((unsigned)(accA[r] & 0xffffffffull))
                 + __uint_as_float((unsigned)(accA[r] >> 32));
        float vB = __uint_as_float((unsigned)(accB[r] & 0xffffffffull))
                 + __uint_as_float((unsigned)(accB[r] >> 32));
        if (RELU) { vA = fmaxf(vA, 0.0f); vB = fmaxf(vB, 0.0f); }
        float* o = out + (size_t)(m0 + r0 + r) * DIM;
        o[c2]       = vA;
        o[128 + c2] = vB;
    }
}

// ============================ layer 0 =======================================
// TM=16, 512 threads, one warp per row (coalesced gathers), 3 CTAs/SM.
// blocks [0,640): n1 (10240 rows, F=25); [640,704): n0 (1024 rows, F=10).
template <int F>
__device__ __forceinline__ void sage0_tile(
    const float4* __restrict__ feat4,
    const int* __restrict__ sidx, const int* __restrict__ nidx,
    float* __restrict__ out, int m0, float4* Xs4, float4* Xn4)
{
    const int tid  = threadIdx.x;
    const int lane = tid & 31;
    const int w    = tid >> 5;       // warp id 0..15 == row within tile
    const int row  = m0 + w;

    // self row (coalesced)
    {
        const size_t gs = (size_t)__ldg(sidx + row);
        float4 s0, s1;
        warp_load_row(feat4, gs, lane, s0, s1);
        Xs4[w * D4 + lane]      = s0;
        Xs4[w * D4 + 32 + lane] = s1;
    }
    // neighbor mean (coalesced)
    {
        float4 n0v, n1v;
        warp_mean_rows<F, true>(feat4, nidx, (size_t)row * F, lane, n0v, n1v);
        Xn4[w * D4 + lane]      = n0v;
        Xn4[w * D4 + 32 + lane] = n1v;
    }
    __syncthreads();

    gemm_tile<16, 512, true>(Xs4, Xn4, g_Wt0, out, m0);
}

__global__ void __launch_bounds__(512, 3)
sage_layer0_kernel(const float4* __restrict__ feat4,
                   const int* __restrict__ sn0,
                   const int* __restrict__ sn1,
                   const int* __restrict__ sn2,
                   float* __restrict__ n1,
                   float* __restrict__ n0)
{
    __shared__ float4 Xs4[16 * D4];
    __shared__ float4 Xn4[16 * D4];
    if (blockIdx.x < 640) {
        sage0_tile<25>(feat4, sn1, sn2, n1, blockIdx.x * 16, Xs4, Xn4);
    } else {
        sage0_tile<10>(feat4, sn0, sn1, n0, (blockIdx.x - 640) * 16, Xs4, Xn4);
    }
}

// ============================ layer 1 =======================================
// TM=4, 256 threads, grid 256. Warps 0-3: neighbor means (10 contiguous n1
// rows each); warps 4-7: self rows from n0. No activation.
__global__ void __launch_bounds__(256)
sage_layer1_kernel(const float4* __restrict__ n0_4,
                   const float4* __restrict__ n1_4,
                   float* __restrict__ out)
{
    __shared__ float4 Xs4[4 * D4];
    __shared__ float4 Xn4[4 * D4];
    const int tid  = threadIdx.x;
    const int lane = tid & 31;
    const int w    = tid >> 5;
    const int m0   = blockIdx.x * 4;

    if (w < 4) {
        float4 a0, a1;
        warp_mean_rows<10, false>(n1_4, nullptr, (size_t)(m0 + w) * 10, lane, a0, a1);
        Xn4[w * D4 + lane]      = a0;
        Xn4[w * D4 + 32 + lane] = a1;
    } else {
        const int w4 = w - 4;
        float4 s0, s1;
        warp_load_row(n0_4, (size_t)(m0 + w4), lane, s0, s1);
        Xs4[w4 * D4 + lane]      = s0;
        Xs4[w4 * D4 + 32 + lane] = s1;
    }
    __syncthreads();

    gemm_tile<4, 256, false>(Xs4, Xn4, g_Wt1, out, m0);
}

// =============================================================================
extern "C" void kernel_launch(void* const* d_in, const int* in_sizes, int n_in,
                              void* d_out, int out_size)
{
    const float4* feat4 = (const float4*)d_in[0];
    const int*    sn0   = (const int*)  d_in[1];
    const int*    sn1   = (const int*)  d_in[2];
    const int*    sn2   = (const int*)  d_in[3];
    const float*  W0s   = (const float*)d_in[4];
    const float*  W0n   = (const float*)d_in[5];
    const float*  W1s   = (const float*)d_in[6];
    const float*  W1n   = (const float*)d_in[7];
    float*        out   = (float*)      d_out;

    float* n1 = nullptr;
    float* n0 = nullptr;
    cudaGetSymbolAddress((void**)&n1, g_n1);
    cudaGetSymbolAddress((void**)&n0, g_n0);

    pack_weights<<<512, 256>>>(W0s, W0n, W1s, W1n);
    sage_layer0_kernel<<<704, 512>>>(feat4, sn0, sn1, sn2, n1, n0);
    sage_layer1_kernel<<<256, 256>>>((const float4*)n0, (const float4*)n1, out);
}

// round 8
// speedup vs baseline: 1.2983x; 1.2983x over previous
#include <cuda_runtime.h>
#include <cstdint>

// Problem constants: B=1024, FANOUTS=[10,25], DIM=256, N_NODES=100000
#define DIM 256
#define D4  64     // DIM/4
#define TM  16     // rows per tile

typedef unsigned long long u64;

// Scratch (device globals; allocation-free per harness rules)
__device__ float g_n1[10240 * DIM];
__device__ float g_n0[1024  * DIM];

__device__ __forceinline__ u64 pack2(float a, float b) {
    u64 r;
    asm("mov.b64 %0, {%1, %2};" : "=l"(r) : "f"(a), "f"(b));
    return r;
}
__device__ __forceinline__ u64 ffma2(u64 a, u64 b, u64 c) {
    u64 d;
    asm("fma.rn.f32x2 %0, %1, %2, %3;" : "=l"(d) : "l"(a), "l"(b), "l"(c));
    return d;
}
__device__ __forceinline__ void cp16(uint32_t dst_smem, const float* src) {
    asm volatile("cp.async.cg.shared.global [%0], [%1], 16;"
                 :: "r"(dst_smem), "l"(src));
}
__device__ __forceinline__ void cp_commit() {
    asm volatile("cp.async.commit_group;");
}
__device__ __forceinline__ void cp_wait0() {
    asm volatile("cp.async.wait_group 0;");
}

extern __shared__ float smem_f[];
// layout: Xs[16][256] | Xn[16][256] | Wb[2][16][256]   = 64 KB

// One tile of TM=16 rows, 512 threads:
//   Xs[r] = ssrc[ sidx? sidx[row] : row ]
//   Xn[r] = mean_{j<F} nsrc[ nidx? nidx[row*F+j] : row*F+j ]
//   out[row][c] = act( (c<128 ? Xs@Ws : Xn@Wn)[c] ),  c in [0,256)
template <int F, bool RELU, bool IDX>
__device__ __forceinline__ void sage_tile(
    const float4* __restrict__ ssrc4, const float4* __restrict__ nsrc4,
    const int* __restrict__ sidx, const int* __restrict__ nidx,
    const float* __restrict__ Ws, const float* __restrict__ Wn, // [256][128]
    float* __restrict__ out, int m0)
{
    float* Xs = smem_f;
    float* Xn = smem_f + TM * DIM;
    float* Wb = smem_f + 2 * TM * DIM;           // [2][16*256]
    const int tid = threadIdx.x;
    const uint32_t wb_base = (uint32_t)__cvta_generic_to_shared(Wb);

    // slab j covers k in [j*16, j*16+16); smem slab layout [k][c] (c: 0-127
    // self, 128-255 neigh). Each thread copies two float4s, coalesced.
    auto load_slab = [&](int j, int bsel) {
        #pragma unroll
        for (int h = 0; h < 2; ++h) {
            const int f  = h * 512 + tid;        // float4 index in slab
            const int k  = f >> 6;
            const int c4 = f & 63;
            const float* src = (c4 < 32)
                ? (Ws + (size_t)(j * 16 + k) * 128 + c4 * 4)
                : (Wn + (size_t)(j * 16 + k) * 128 + (c4 - 32) * 4);
            cp16(wb_base + (uint32_t)(bsel * 16384 + f * 16), src);
        }
        cp_commit();
    };

    // prefetch slab 0 first — its latency hides behind the whole gather
    load_slab(0, 0);

    // ---- gather + mean (lane-coalesced: warp lanes share a row) ----
    #pragma unroll
    for (int it = 0; it < 2; ++it) {
        const int i = it * 512 + tid;
        const int r = i >> 6, q = i & 63;
        const int row = m0 + r;
        const int gs = IDX ? __ldg(sidx + row) : row;
        reinterpret_cast<float4*>(Xs)[i] = __ldcg(ssrc4 + (size_t)gs * D4 + q);

        float4 a0 = make_float4(0.f, 0.f, 0.f, 0.f), a1 = a0;
        const size_t nb = (size_t)row * F;
        #pragma unroll
        for (int j2 = 0; j2 < F; j2 += 2) {
            const size_t g0 = IDX ? (size_t)__ldg(nidx + nb + j2) : nb + j2;
            const float4 v = __ldcg(nsrc4 + g0 * D4 + q);
            a0.x += v.x; a0.y += v.y; a0.z += v.z; a0.w += v.w;
            if (j2 + 1 < F) {
                const size_t g1 = IDX ? (size_t)__ldg(nidx + nb + j2 + 1) : nb + j2 + 1;
                const float4 w = __ldcg(nsrc4 + g1 * D4 + q);
                a1.x += w.x; a1.y += w.y; a1.z += w.z; a1.w += w.w;
            }
        }
        const float inv = 1.0f / (float)F;
        float4 o;
        o.x = (a0.x + a1.x) * inv; o.y = (a0.y + a1.y) * inv;
        o.z = (a0.z + a1.z) * inv; o.w = (a0.w + a1.w) * inv;
        reinterpret_cast<float4*>(Xn)[i] = o;
    }

    // ---- GEMM: thread -> (column c, 8-row group); W slabs double-buffered --
    const int c  = tid & 255;
    const int r0 = (tid >> 8) * 8;
    const float* X = (c < 128) ? Xs : Xn;      // warp-uniform select

    u64 acc[8];
    #pragma unroll
    for (int r = 0; r < 8; ++r) acc[r] = 0ull;

    #pragma unroll 1
    for (int j = 0; j < 16; ++j) {
        cp_wait0();
        __syncthreads();   // slab j visible to all; also fences X (j==0) and
                           // prior slab reads (buffer reuse safety)
        if (j < 15) load_slab(j + 1, (j + 1) & 1);

        const float* Wc = Wb + (j & 1) * 4096 + c;   // [k][c], lane-coalesced
        #pragma unroll
        for (int k4 = 0; k4 < 4; ++k4) {
            const u64 wA = pack2(Wc[(4 * k4 + 0) * 256], Wc[(4 * k4 + 1) * 256]);
            const u64 wB = pack2(Wc[(4 * k4 + 2) * 256], Wc[(4 * k4 + 3) * 256]);
            #pragma unroll
            for (int r = 0; r < 8; ++r) {
                const ulonglong2 xv = *reinterpret_cast<const ulonglong2*>(
                    X + (r0 + r) * DIM + j * 16 + k4 * 4);   // broadcast LDS
                acc[r] = ffma2(xv.x, wA, acc[r]);
                acc[r] = ffma2(xv.y, wB, acc[r]);
            }
        }
    }

    #pragma unroll
    for (int r = 0; r < 8; ++r) {
        float v = __uint_as_float((unsigned)(acc[r] & 0xffffffffull))
                + __uint_as_float((unsigned)(acc[r] >> 32));
        if (RELU) v = fmaxf(v, 0.0f);
        out[(size_t)(m0 + r0 + r) * DIM + c] = v;
    }
}

// K1: layer 0. blocks [0,640): n1 tiles (F=25); [640,704): n0 tiles (F=10).
__global__ void __launch_bounds__(512)
sage_layer0_kernel(const float4* __restrict__ feat4,
                   const int* __restrict__ sn0,
                   const int* __restrict__ sn1,
                   const int* __restrict__ sn2,
                   const float* __restrict__ W0s,
                   const float* __restrict__ W0n,
                   float* __restrict__ n1,
                   float* __restrict__ n0)
{
    if (blockIdx.x < 640) {
        sage_tile<25, true, true>(feat4, feat4, sn1, sn2, W0s, W0n,
                                  n1, blockIdx.x * TM);
    } else {
        sage_tile<10, true, true>(feat4, feat4, sn0, sn1, W0s, W0n,
                                  n0, (blockIdx.x - 640) * TM);
    }
}

// K2: layer 1 (no activation). self = n0 row, neigh = mean10 of contiguous
// n1 rows. 1024 rows / TM=16 -> 64 CTAs.
__global__ void __launch_bounds__(512)
sage_layer1_kernel(const float4* __restrict__ n0_4,
                   const float4* __restrict__ n1_4,
                   const float* __restrict__ W1s,
                   const float* __restrict__ W1n,
                   float* __restrict__ out)
{
    sage_tile<10, false, false>(n0_4, n1_4, nullptr, nullptr, W1s, W1n,
                                out, blockIdx.x * TM);
}

// =============================================================================
extern "C" void kernel_launch(void* const* d_in, const int* in_sizes, int n_in,
                              void* d_out, int out_size)
{
    const float4* feat4 = (const float4*)d_in[0];
    const int*    sn0   = (const int*)  d_in[1];
    const int*    sn1   = (const int*)  d_in[2];
    const int*    sn2   = (const int*)  d_in[3];
    const float*  W0s   = (const float*)d_in[4];
    const float*  W0n   = (const float*)d_in[5];
    const float*  W1s   = (const float*)d_in[6];
    const float*  W1n   = (const float*)d_in[7];
    float*        out   = (float*)      d_out;

    float* n1 = nullptr;
    float* n0 = nullptr;
    cudaGetSymbolAddress((void**)&n1, g_n1);
    cudaGetSymbolAddress((void**)&n0, g_n0);

    const int SMEM = 64 * 1024;   // Xs 16KB + Xn 16KB + W double-buffer 32KB
    static bool attr_set = false;
    if (!attr_set) {
        cudaFuncSetAttribute(sage_layer0_kernel,
                             cudaFuncAttributeMaxDynamicSharedMemorySize, SMEM);
        cudaFuncSetAttribute(sage_layer1_kernel,
                             cudaFuncAttributeMaxDynamicSharedMemorySize, SMEM);
        attr_set = true;
    }

    sage_layer0_kernel<<<704, 512, SMEM>>>(feat4, sn0, sn1, sn2, W0s, W0n, n1, n0);
    sage_layer1_kernel<<<64, 512, SMEM>>>((const float4*)n0, (const float4*)n1,
                                          W1s, W1n, out);
}

// round 9
// speedup vs baseline: 1.3012x; 1.0022x over previous
#include <cuda_runtime.h>
#include <cstdint>

// Problem constants: B=1024, FANOUTS=[10,25], DIM=256, N_NODES=100000
#define DIM 256
#define D4  64     // DIM/4
#define TM  16     // rows per tile

typedef unsigned long long u64;

// Scratch (device globals; allocation-free per harness rules)
__device__ float g_n1[10240 * DIM];
__device__ float g_n0[1024  * DIM];

__device__ __forceinline__ u64 pack2(float a, float b) {
    u64 r;
    asm("mov.b64 %0, {%1, %2};" : "=l"(r) : "f"(a), "f"(b));
    return r;
}
__device__ __forceinline__ u64 ffma2(u64 a, u64 b, u64 c) {
    u64 d;
    asm("fma.rn.f32x2 %0, %1, %2, %3;" : "=l"(d) : "l"(a), "l"(b), "l"(c));
    return d;
}
__device__ __forceinline__ void cp16(uint32_t dst_smem, const float* src) {
    asm volatile("cp.async.cg.shared.global [%0], [%1], 16;"
                 :: "r"(dst_smem), "l"(src));
}
__device__ __forceinline__ void cp_commit() {
    asm volatile("cp.async.commit_group;");
}
__device__ __forceinline__ void cp_wait0() {
    asm volatile("cp.async.wait_group 0;");
}

extern __shared__ float smem_f[];
// layout: Xs[16][256] | Xn[16][256] | Wb[2][16][256]   = 64 KB

// One tile of TM=16 rows, 512 threads:
//   Xs[r] = ssrc[ sidx? sidx[row] : row ]
//   Xn[r] = mean_{j<F} nsrc[ nidx? nidx[row*F+j] : row*F+j ]
//   out[row][c] = act( (c<128 ? Xs@Ws : Xn@Wn)[c] ),  c in [0,256)
template <int F, bool RELU, bool IDX>
__device__ __forceinline__ void sage_tile(
    const float4* __restrict__ ssrc4, const float4* __restrict__ nsrc4,
    const int* __restrict__ sidx, const int* __restrict__ nidx,
    const float* __restrict__ Ws, const float* __restrict__ Wn, // [256][128]
    float* __restrict__ out, int m0)
{
    float* Xs = smem_f;
    float* Xn = smem_f + TM * DIM;
    float* Wb = smem_f + 2 * TM * DIM;           // [2][16*256]
    const int tid = threadIdx.x;
    const uint32_t wb_base = (uint32_t)__cvta_generic_to_shared(Wb);

    // slab j covers k in [j*16, j*16+16); smem slab layout [k][c] (c: 0-127
    // self, 128-255 neigh). Each thread copies two float4s, coalesced.
    auto load_slab = [&](int j, int bsel) {
        #pragma unroll
        for (int h = 0; h < 2; ++h) {
            const int f  = h * 512 + tid;        // float4 index in slab
            const int k  = f >> 6;
            const int c4 = f & 63;
            const float* src = (c4 < 32)
                ? (Ws + (size_t)(j * 16 + k) * 128 + c4 * 4)
                : (Wn + (size_t)(j * 16 + k) * 128 + (c4 - 32) * 4);
            cp16(wb_base + (uint32_t)(bsel * 16384 + f * 16), src);
        }
        cp_commit();
    };

    // prefetch slab 0 first — its latency hides behind the whole gather
    load_slab(0, 0);

    // ---- gather + mean (lane-coalesced: warp lanes share a row) ----
    #pragma unroll
    for (int it = 0; it < 2; ++it) {
        const int i = it * 512 + tid;
        const int r = i >> 6, q = i & 63;
        const int row = m0 + r;
        const int gs = IDX ? __ldg(sidx + row) : row;
        reinterpret_cast<float4*>(Xs)[i] = __ldcg(ssrc4 + (size_t)gs * D4 + q);

        float4 a0 = make_float4(0.f, 0.f, 0.f, 0.f), a1 = a0;
        const size_t nb = (size_t)row * F;
        #pragma unroll
        for (int j2 = 0; j2 < F; j2 += 2) {
            const size_t g0 = IDX ? (size_t)__ldg(nidx + nb + j2) : nb + j2;
            const float4 v = __ldcg(nsrc4 + g0 * D4 + q);
            a0.x += v.x; a0.y += v.y; a0.z += v.z; a0.w += v.w;
            if (j2 + 1 < F) {
                const size_t g1 = IDX ? (size_t)__ldg(nidx + nb + j2 + 1) : nb + j2 + 1;
                const float4 w = __ldcg(nsrc4 + g1 * D4 + q);
                a1.x += w.x; a1.y += w.y; a1.z += w.z; a1.w += w.w;
            }
        }
        const float inv = 1.0f / (float)F;
        float4 o;
        o.x = (a0.x + a1.x) * inv; o.y = (a0.y + a1.y) * inv;
        o.z = (a0.z + a1.z) * inv; o.w = (a0.w + a1.w) * inv;
        reinterpret_cast<float4*>(Xn)[i] = o;
    }

    // ---- GEMM: thread -> (column c, 8-row group); W slabs double-buffered --
    const int c  = tid & 255;
    const int r0 = (tid >> 8) * 8;
    const float* X = (c < 128) ? Xs : Xn;      // warp-uniform select

    u64 acc[8];
    #pragma unroll
    for (int r = 0; r < 8; ++r) acc[r] = 0ull;

    #pragma unroll 1
    for (int j = 0; j < 16; ++j) {
        cp_wait0();
        __syncthreads();   // slab j visible to all; also fences X (j==0) and
                           // prior slab reads (buffer reuse safety)
        if (j < 15) load_slab(j + 1, (j + 1) & 1);

        const float* Wc = Wb + (j & 1) * 4096 + c;   // [k][c], lane-coalesced
        #pragma unroll
        for (int k4 = 0; k4 < 4; ++k4) {
            const u64 wA = pack2(Wc[(4 * k4 + 0) * 256], Wc[(4 * k4 + 1) * 256]);
            const u64 wB = pack2(Wc[(4 * k4 + 2) * 256], Wc[(4 * k4 + 3) * 256]);
            #pragma unroll
            for (int r = 0; r < 8; ++r) {
                const ulonglong2 xv = *reinterpret_cast<const ulonglong2*>(
                    X + (r0 + r) * DIM + j * 16 + k4 * 4);   // broadcast LDS
                acc[r] = ffma2(xv.x, wA, acc[r]);
                acc[r] = ffma2(xv.y, wB, acc[r]);
            }
        }
    }

    #pragma unroll
    for (int r = 0; r < 8; ++r) {
        float v = __uint_as_float((unsigned)(acc[r] & 0xffffffffull))
                + __uint_as_float((unsigned)(acc[r] >> 32));
        if (RELU) v = fmaxf(v, 0.0f);
        out[(size_t)(m0 + r0 + r) * DIM + c] = v;
    }
}

// K1: layer 0. blocks [0,640): n1 tiles (F=25); [640,704): n0 tiles (F=10).
__global__ void __launch_bounds__(512)
sage_layer0_kernel(const float4* __restrict__ feat4,
                   const int* __restrict__ sn0,
                   const int* __restrict__ sn1,
                   const int* __restrict__ sn2,
                   const float* __restrict__ W0s,
                   const float* __restrict__ W0n,
                   float* __restrict__ n1,
                   float* __restrict__ n0)
{
    if (blockIdx.x < 640) {
        sage_tile<25, true, true>(feat4, feat4, sn1, sn2, W0s, W0n,
                                  n1, blockIdx.x * TM);
    } else {
        sage_tile<10, true, true>(feat4, feat4, sn0, sn1, W0s, W0n,
                                  n0, (blockIdx.x - 640) * TM);
    }
}

// K2: layer 1 (no activation). self = n0 row, neigh = mean10 of contiguous
// n1 rows. 1024 rows / TM=16 -> 64 CTAs.
__global__ void __launch_bounds__(512)
sage_layer1_kernel(const float4* __restrict__ n0_4,
                   const float4* __restrict__ n1_4,
                   const float* __restrict__ W1s,
                   const float* __restrict__ W1n,
                   float* __restrict__ out)
{
    sage_tile<10, false, false>(n0_4, n1_4, nullptr, nullptr, W1s, W1n,
                                out, blockIdx.x * TM);
}

// =============================================================================
extern "C" void kernel_launch(void* const* d_in, const int* in_sizes, int n_in,
                              void* d_out, int out_size)
{
    const float4* feat4 = (const float4*)d_in[0];
    const int*    sn0   = (const int*)  d_in[1];
    const int*    sn1   = (const int*)  d_in[2];
    const int*    sn2   = (const int*)  d_in[3];
    const float*  W0s   = (const float*)d_in[4];
    const float*  W0n   = (const float*)d_in[5];
    const float*  W1s   = (const float*)d_in[6];
    const float*  W1n   = (const float*)d_in[7];
    float*        out   = (float*)      d_out;

    float* n1 = nullptr;
    float* n0 = nullptr;
    cudaGetSymbolAddress((void**)&n1, g_n1);
    cudaGetSymbolAddress((void**)&n0, g_n0);

    const int SMEM = 64 * 1024;   // Xs 16KB + Xn 16KB + W double-buffer 32KB
    static bool attr_set = false;
    if (!attr_set) {
        cudaFuncSetAttribute(sage_layer0_kernel,
                             cudaFuncAttributeMaxDynamicSharedMemorySize, SMEM);
        cudaFuncSetAttribute(sage_layer1_kernel,
                             cudaFuncAttributeMaxDynamicSharedMemorySize, SMEM);
        attr_set = true;
    }

    sage_layer0_kernel<<<704, 512, SMEM>>>(feat4, sn0, sn1, sn2, W0s, W0n, n1, n0);
    sage_layer1_kernel<<<64, 512, SMEM>>>((const float4*)n0, (const float4*)n1,
                                          W1s, W1n, out);
}